// round 14
// baseline (speedup 1.0000x reference)
#include <cuda_runtime.h>
#include <cuda_fp16.h>

#define S        128
#define N_LGN    17400
#define N_POST   50000
#define NNZ      800000
#define NBASIS   5
#define N_RECEPT 10
#define OUT_ROW  (N_POST * NBASIS)   // 250000
#define RPB      8                   // rows per block
#define CAP      64                  // bucket capacity (Poisson(16); P(>64) ~ 1e-32)
#define PREP_BLKS 544                // ceil(17400/32)
#define SCAT_BLKS ((NNZ + 511) / 512)

// ---------------- device scratch (no allocations allowed) ----------------
// xTh layout: uint2 at [c*32 + lane] = 4 halves x[s = {lane, lane+32, lane+64, lane+96}][c]
// g_cnt invariant: zero at entry of every kernel_launch execution (module-load
// zero-init covers the first call; k_spmm resets each row after reading it).
__device__ __half g_xTh[N_LGN * S];
__device__ int    g_cnt[N_POST];
__device__ int4   g_meta[(size_t)N_POST * CAP];  // {col*256, sid*48, w_bits, 0}

typedef unsigned long long ull;
__device__ __forceinline__ void ffma2(ull &d, ull a, ull b) {
    asm("fma.rn.f32x2 %0, %1, %2, %0;" : "+l"(d) : "l"(a), "l"(b));
}
__device__ __forceinline__ ull pack2(float x, float y) {
    ull r;
    asm("mov.b64 %0, {%1, %2};" : "=l"(r) : "f"(x), "f"(y));
    return r;
}
__device__ __forceinline__ float2 unpack2(ull v) {
    float2 f;
    asm("mov.b64 {%0, %1}, %2;" : "=f"(f.x), "=f"(f.y) : "l"(v));
    return f;
}

// ------------- 1) fused: transpose/pack x  ||  bucket scatter -------------
__global__ void __launch_bounds__(512) k_pre(const float* __restrict__ x,
                                             const int2*  __restrict__ idx,
                                             const float* __restrict__ w,
                                             const int*   __restrict__ sids) {
    __shared__ float tile[S][33];
    int tid = threadIdx.x;

    if (blockIdx.x < PREP_BLKS) {
        // ---- transpose x[s][c] -> permuted fp16 pack ----
        int tx = tid & 31, ty = tid >> 5;    // (32,16)
        int c0 = blockIdx.x * 32;
        int c = c0 + tx;
        bool cok = (c < N_LGN);
        #pragma unroll
        for (int j = ty; j < S; j += 16)
            tile[j][tx] = cok ? x[j * N_LGN + c] : 0.f;
        __syncthreads();

        uint2* xb = (uint2*)g_xTh;
        #pragma unroll
        for (int cl = ty; cl < 32; cl += 16) {
            int cc = c0 + cl;
            if (cc < N_LGN) {
                __half2 h01 = __floats2half2_rn(tile[tx][cl],      tile[tx + 32][cl]);
                __half2 h23 = __floats2half2_rn(tile[tx + 64][cl], tile[tx + 96][cl]);
                uint2 v;
                v.x = *(unsigned int*)&h01;
                v.y = *(unsigned int*)&h23;
                xb[cc * 32 + tx] = v;
            }
        }
    } else {
        // ---- scatter: 16B meta, offsets premultiplied ----
        int e = (blockIdx.x - PREP_BLKS) * 512 + tid;
        if (e >= NNZ) return;
        int2 rc = idx[e];
        int p = atomicAdd(&g_cnt[rc.x], 1);
        if (p < CAP)
            g_meta[(size_t)rc.x * CAP + p] =
                make_int4(rc.y * 256, sids[e] * 48, __float_as_int(w[e]), 0);
    }
}

// ---------------- per-edge math (EXACT R10 source — do not perturb) --------
__device__ __forceinline__ void edge_math(unsigned fa, int w_bits, uint2 xh,
                                          ull acc[NBASIS][2]) {
    float w = __int_as_float(w_bits);
    float2 x01 = __half22float2(*(__half2*)&xh.x);   // s = lane, lane+32
    float2 x23 = __half22float2(*(__half2*)&xh.y);   // s = lane+64, lane+96
    ull ww, xwa, xwc;
    asm("mov.b64 %0, {%1, %1};" : "=l"(ww) : "f"(w));
    ull xa = pack2(x01.x, x01.y);
    ull xc = pack2(x23.x, x23.y);
    asm("mul.rn.f32x2 %0, %1, %2;" : "=l"(xwa) : "l"(xa), "l"(ww));
    asm("mul.rn.f32x2 %0, %1, %2;" : "=l"(xwc) : "l"(xc), "l"(ww));
    ull f0, f1, f2, f3, f4;
    asm("ld.shared.v2.u64 {%0, %1}, [%2];"      : "=l"(f0), "=l"(f1) : "r"(fa));
    asm("ld.shared.v2.u64 {%0, %1}, [%2 + 16];" : "=l"(f2), "=l"(f3) : "r"(fa));
    asm("ld.shared.u64 %0, [%1 + 32];"          : "=l"(f4) : "r"(fa));
    ffma2(acc[0][0], xwa, f0); ffma2(acc[0][1], xwc, f0);
    ffma2(acc[1][0], xwa, f1); ffma2(acc[1][1], xwc, f1);
    ffma2(acc[2][0], xwa, f2); ffma2(acc[2][1], xwc, f2);
    ffma2(acc[3][0], xwa, f3); ffma2(acc[3][1], xwc, f3);
    ffma2(acc[4][0], xwa, f4); ffma2(acc[4][1], xwc, f4);
}

// ------- 2) main SpMM (R10 source; only delta: g_cnt self-reset) -----------
__global__ void __launch_bounds__(128, 8) k_spmm(float* __restrict__ out,
                                                 const float* __restrict__ synw) {
    __shared__ __align__(16) float  sh[S * 44];          // stride 44: 16B-aligned rows
    __shared__ __align__(16) float2 fsh2[N_RECEPT * 6];  // dup pairs, 48B per sid
    int tid = threadIdx.x;
    if (tid < N_RECEPT * 6) {
        int sid = tid / 6, r = tid - sid * 6;
        float v = (r < NBASIS) ? synw[sid * NBASIS + r] : 0.f;
        fsh2[tid] = make_float2(v, v);
    }
    __syncthreads();
    unsigned fbase = (unsigned)__cvta_generic_to_shared(fsh2);

    int warp = tid >> 5;
    int lane = tid & 31;
    int n0 = blockIdx.x * RPB;
    const char* xlane = (const char*)g_xTh + lane * 8;

    #pragma unroll
    for (int rr = 0; rr < 2; rr++) {
        int n = n0 + warp * 2 + rr;
        int len = g_cnt[n];
        if (lane == 0) g_cnt[n] = 0;      // restore invariant for next replay
        if (len > CAP) len = CAP;
        const int4* pm = g_meta + (size_t)n * CAP;

        ull acc[NBASIS][2];
        #pragma unroll
        for (int r = 0; r < NBASIS; r++) { acc[r][0] = 0ull; acc[r][1] = 0ull; }

        for (int seg = 0; seg * 32 < len; seg++) {
            int4 m = __ldg(pm + seg * 32 + lane);   // 32 edges' meta in warp regs
            int cnt = len - seg * 32;
            if (cnt > 32) cnt = 32;

            int j = 0;
            #pragma unroll 1
            for (; j + 4 <= cnt; j += 4) {
                uint2 xv[4];
                #pragma unroll
                for (int t = 0; t < 4; t++) {
                    int mx = __shfl_sync(0xFFFFFFFFu, m.x, j + t);
                    xv[t] = __ldg((const uint2*)(xlane + mx));   // MLP 4, 2 wf each
                }
                #pragma unroll
                for (int t = 0; t < 4; t++) {
                    int my = __shfl_sync(0xFFFFFFFFu, m.y, j + t);
                    int mw = __shfl_sync(0xFFFFFFFFu, m.z, j + t);
                    edge_math(fbase + (unsigned)my, mw, xv[t], acc);
                }
            }
            for (; j < cnt; j++) {
                int mx = __shfl_sync(0xFFFFFFFFu, m.x, j);
                int my = __shfl_sync(0xFFFFFFFFu, m.y, j);
                int mw = __shfl_sync(0xFFFFFFFFu, m.z, j);
                uint2 xv = __ldg((const uint2*)(xlane + mx));
                edge_math(fbase + (unsigned)my, mw, xv, acc);
            }
        }

        // stage row (warp*2+rr): lane's values are s = {lane, +32, +64, +96}
        int rl = (warp * 2 + rr) * NBASIS;
        #pragma unroll
        for (int r = 0; r < NBASIS; r++) {
            float2 lo = unpack2(acc[r][0]);
            float2 hi = unpack2(acc[r][1]);
            sh[(lane      ) * 44 + rl + r] = lo.x;
            sh[(lane + 32 ) * 44 + rl + r] = lo.y;
            sh[(lane + 64 ) * 44 + rl + r] = hi.x;
            sh[(lane + 96 ) * 44 + rl + r] = hi.y;
        }
    }
    __syncthreads();

    // vectorized write-out: 1280 float4 = 128 s x 10 q; 10 iters per thread
    const float4* sh4 = (const float4*)sh;           // 11 float4 per s-row
    float* op = out + (size_t)n0 * NBASIS;
    #pragma unroll
    for (int it = 0; it < 10; it++) {
        int idx = it * 128 + tid;
        int s = idx / 10;
        int q = idx - s * 10;
        float4 v = sh4[s * 11 + q];
        *(float4*)(op + (size_t)s * OUT_ROW + q * 4) = v;
    }
}

// ---------------- launch ----------------
extern "C" void kernel_launch(void* const* d_in, const int* in_sizes, int n_in,
                              void* d_out, int out_size) {
    const float* inp     = (const float*)d_in[0];
    const int2*  indices = (const int2*)d_in[1];
    const float* weights = (const float*)d_in[2];
    const float* synw    = (const float*)d_in[3];
    const int*   sids    = (const int*)d_in[4];
    float*       out     = (float*)d_out;
    (void)in_sizes; (void)n_in; (void)out_size;

    k_pre<<<PREP_BLKS + SCAT_BLKS, 512>>>(inp, indices, weights, sids);
    k_spmm<<<N_POST / RPB, 128>>>(out, synw);
}

// round 15
// speedup vs baseline: 1.2640x; 1.2640x over previous
#include <cuda_runtime.h>
#include <cuda_fp16.h>

#define S        128
#define N_LGN    17400
#define N_POST   50000
#define NNZ      800000
#define NBASIS   5
#define N_RECEPT 10
#define OUT_ROW  (N_POST * NBASIS)   // 250000
#define RPB      4                   // rows per block (one per warp)
#define CAP      64                  // bucket capacity (Poisson(16); P(>64) ~ 1e-32)
#define PREP_BLKS 544                // ceil(17400/32)
#define SCAT_BLKS ((NNZ + 511) / 512)

// ---------------- device scratch (no allocations allowed) ----------------
// xTh layout: uint2 at [c*32 + lane] = 4 halves x[s = {lane, lane+32, lane+64, lane+96}][c]
__device__ __half g_xTh[N_LGN * S];
__device__ int    g_cnt[N_POST];
__device__ int4   g_meta[(size_t)N_POST * CAP];  // {col*256, sid*48, w_bits, 0}

typedef unsigned long long ull;
__device__ __forceinline__ void ffma2(ull &d, ull a, ull b) {
    asm("fma.rn.f32x2 %0, %1, %2, %0;" : "+l"(d) : "l"(a), "l"(b));
}
__device__ __forceinline__ ull pack2(float x, float y) {
    ull r;
    asm("mov.b64 %0, {%1, %2};" : "=l"(r) : "f"(x), "f"(y));
    return r;
}
__device__ __forceinline__ float2 unpack2(ull v) {
    float2 f;
    asm("mov.b64 {%0, %1}, %2;" : "=f"(f.x), "=f"(f.y) : "l"(v));
    return f;
}

// ---------------- 0) zero counters (must precede scatter atomics) ----------
__global__ void k_zero() {
    int i = blockIdx.x * blockDim.x + threadIdx.x;
    if (i < N_POST) g_cnt[i] = 0;
}

// ------------- 1) fused: transpose/pack x  ||  bucket scatter -------------
__global__ void __launch_bounds__(512) k_pre(const float* __restrict__ x,
                                             const int2*  __restrict__ idx,
                                             const float* __restrict__ w,
                                             const int*   __restrict__ sids) {
    __shared__ float tile[S][33];
    int tid = threadIdx.x;

    if (blockIdx.x < PREP_BLKS) {
        // ---- transpose x[s][c] -> permuted fp16 pack ----
        int tx = tid & 31, ty = tid >> 5;    // (32,16)
        int c0 = blockIdx.x * 32;
        int c = c0 + tx;
        bool cok = (c < N_LGN);
        #pragma unroll
        for (int j = ty; j < S; j += 16)
            tile[j][tx] = cok ? x[j * N_LGN + c] : 0.f;
        __syncthreads();

        uint2* xb = (uint2*)g_xTh;
        #pragma unroll
        for (int cl = ty; cl < 32; cl += 16) {
            int cc = c0 + cl;
            if (cc < N_LGN) {
                __half2 h01 = __floats2half2_rn(tile[tx][cl],      tile[tx + 32][cl]);
                __half2 h23 = __floats2half2_rn(tile[tx + 64][cl], tile[tx + 96][cl]);
                uint2 v;
                v.x = *(unsigned int*)&h01;
                v.y = *(unsigned int*)&h23;
                xb[cc * 32 + tx] = v;
            }
        }
    } else {
        // ---- scatter: 16B meta, offsets premultiplied ----
        int e = (blockIdx.x - PREP_BLKS) * 512 + tid;
        if (e >= NNZ) return;
        int2 rc = idx[e];
        int p = atomicAdd(&g_cnt[rc.x], 1);
        if (p < CAP)
            g_meta[(size_t)rc.x * CAP + p] =
                make_int4(rc.y * 256, sids[e] * 48, __float_as_int(w[e]), 0);
    }
}

// ---------------- per-edge math (EXACT R10 source — do not perturb) --------
__device__ __forceinline__ void edge_math(unsigned fa, int w_bits, uint2 xh,
                                          ull acc[NBASIS][2]) {
    float w = __int_as_float(w_bits);
    float2 x01 = __half22float2(*(__half2*)&xh.x);   // s = lane, lane+32
    float2 x23 = __half22float2(*(__half2*)&xh.y);   // s = lane+64, lane+96
    ull ww, xwa, xwc;
    asm("mov.b64 %0, {%1, %1};" : "=l"(ww) : "f"(w));
    ull xa = pack2(x01.x, x01.y);
    ull xc = pack2(x23.x, x23.y);
    asm("mul.rn.f32x2 %0, %1, %2;" : "=l"(xwa) : "l"(xa), "l"(ww));
    asm("mul.rn.f32x2 %0, %1, %2;" : "=l"(xwc) : "l"(xc), "l"(ww));
    ull f0, f1, f2, f3, f4;
    asm("ld.shared.v2.u64 {%0, %1}, [%2];"      : "=l"(f0), "=l"(f1) : "r"(fa));
    asm("ld.shared.v2.u64 {%0, %1}, [%2 + 16];" : "=l"(f2), "=l"(f3) : "r"(fa));
    asm("ld.shared.u64 %0, [%1 + 32];"          : "=l"(f4) : "r"(fa));
    ffma2(acc[0][0], xwa, f0); ffma2(acc[0][1], xwc, f0);
    ffma2(acc[1][0], xwa, f1); ffma2(acc[1][1], xwc, f1);
    ffma2(acc[2][0], xwa, f2); ffma2(acc[2][1], xwc, f2);
    ffma2(acc[3][0], xwa, f3); ffma2(acc[3][1], xwc, f3);
    ffma2(acc[4][0], xwa, f4); ffma2(acc[4][1], xwc, f4);
}

// -------- 2) main SpMM: 128 thr, 4 warps x 1 row (inner loop = R10) --------
__global__ void __launch_bounds__(128, 8) k_spmm(float* __restrict__ out,
                                                 const float* __restrict__ synw) {
    __shared__ __align__(16) float  sh[S * 28];          // stride 28: 16B-aligned rows
    __shared__ __align__(16) float2 fsh2[N_RECEPT * 6];  // dup pairs, 48B per sid
    int tid = threadIdx.x;
    if (tid < N_RECEPT * 6) {
        int sid = tid / 6, r = tid - sid * 6;
        float v = (r < NBASIS) ? synw[sid * NBASIS + r] : 0.f;
        fsh2[tid] = make_float2(v, v);
    }
    __syncthreads();
    unsigned fbase = (unsigned)__cvta_generic_to_shared(fsh2);

    int warp = tid >> 5;
    int lane = tid & 31;
    int n0 = blockIdx.x * RPB;
    const char* xlane = (const char*)g_xTh + lane * 8;

    {
        int n = n0 + warp;
        int len = g_cnt[n];
        if (len > CAP) len = CAP;
        const int4* pm = g_meta + (size_t)n * CAP;

        ull acc[NBASIS][2];
        #pragma unroll
        for (int r = 0; r < NBASIS; r++) { acc[r][0] = 0ull; acc[r][1] = 0ull; }

        for (int seg = 0; seg * 32 < len; seg++) {
            int4 m = __ldg(pm + seg * 32 + lane);   // 32 edges' meta in warp regs
            int cnt = len - seg * 32;
            if (cnt > 32) cnt = 32;

            int j = 0;
            #pragma unroll 1
            for (; j + 4 <= cnt; j += 4) {
                uint2 xv[4];
                #pragma unroll
                for (int t = 0; t < 4; t++) {
                    int mx = __shfl_sync(0xFFFFFFFFu, m.x, j + t);
                    xv[t] = __ldg((const uint2*)(xlane + mx));   // MLP 4, 2 wf each
                }
                #pragma unroll
                for (int t = 0; t < 4; t++) {
                    int my = __shfl_sync(0xFFFFFFFFu, m.y, j + t);
                    int mw = __shfl_sync(0xFFFFFFFFu, m.z, j + t);
                    edge_math(fbase + (unsigned)my, mw, xv[t], acc);
                }
            }
            for (; j < cnt; j++) {
                int mx = __shfl_sync(0xFFFFFFFFu, m.x, j);
                int my = __shfl_sync(0xFFFFFFFFu, m.y, j);
                int mw = __shfl_sync(0xFFFFFFFFu, m.z, j);
                uint2 xv = __ldg((const uint2*)(xlane + mx));
                edge_math(fbase + (unsigned)my, mw, xv, acc);
            }
        }

        // stage row: lane's values are s = {lane, +32, +64, +96}
        int rl = warp * NBASIS;
        #pragma unroll
        for (int r = 0; r < NBASIS; r++) {
            float2 lo = unpack2(acc[r][0]);
            float2 hi = unpack2(acc[r][1]);
            sh[(lane      ) * 28 + rl + r] = lo.x;
            sh[(lane + 32 ) * 28 + rl + r] = lo.y;
            sh[(lane + 64 ) * 28 + rl + r] = hi.x;
            sh[(lane + 96 ) * 28 + rl + r] = hi.y;
        }
    }
    __syncthreads();

    // vectorized write-out: 640 float4 = 128 s x 5 q; 5 iters per thread
    const float4* sh4 = (const float4*)sh;           // 7 float4 per s-row
    float* op = out + (size_t)n0 * NBASIS;
    #pragma unroll
    for (int it = 0; it < 5; it++) {
        int idx = it * 128 + tid;
        int s = idx / 5;
        int q = idx - s * 5;
        float4 v = sh4[s * 7 + q];
        *(float4*)(op + (size_t)s * OUT_ROW + q * 4) = v;
    }
}

// ---------------- launch ----------------
extern "C" void kernel_launch(void* const* d_in, const int* in_sizes, int n_in,
                              void* d_out, int out_size) {
    const float* inp     = (const float*)d_in[0];
    const int2*  indices = (const int2*)d_in[1];
    const float* weights = (const float*)d_in[2];
    const float* synw    = (const float*)d_in[3];
    const int*   sids    = (const int*)d_in[4];
    float*       out     = (float*)d_out;
    (void)in_sizes; (void)n_in; (void)out_size;

    k_zero<<<(N_POST + 255) / 256, 256>>>();
    k_pre<<<PREP_BLKS + SCAT_BLKS, 512>>>(inp, indices, weights, sids);
    k_spmm<<<N_POST / RPB, 128>>>(out, synw);
}

// round 16
// speedup vs baseline: 1.2941x; 1.0238x over previous
#include <cuda_runtime.h>
#include <cuda_fp16.h>

#define S        128
#define N_LGN    17400
#define N_POST   50000
#define NNZ      800000
#define NBASIS   5
#define N_RECEPT 10
#define OUT_ROW  (N_POST * NBASIS)   // 250000
#define RPB      8                   // rows per block
#define CAP      64                  // bucket capacity (Poisson(16); P(>64) ~ 1e-32)
#define ZERO_BLKS 25                 // 25*512 int4 = 51200 int4 >= 12500 needed
#define PREP_BLKS 544                // ceil(17400/32)
#define SCAT_BLKS ((NNZ + 511) / 512)

// ---------------- device scratch (no allocations allowed) ----------------
// xTh layout: uint2 at [c*32 + lane] = 4 halves x[s = {lane, lane+32, lane+64, lane+96}][c]
__device__ __half g_xTh[N_LGN * S];
__device__ int    g_cnt[N_POST];
__device__ int4   g_meta[(size_t)N_POST * CAP];  // {col*256, sid*48, w_bits, 0}
// handshake counters; invariant: 0 at entry of every execution (zero-init at
// module load; last-finishing scatter block restores them each execution)
__device__ int    g_done;
__device__ int    g_exit;

typedef unsigned long long ull;
__device__ __forceinline__ void ffma2(ull &d, ull a, ull b) {
    asm("fma.rn.f32x2 %0, %1, %2, %0;" : "+l"(d) : "l"(a), "l"(b));
}
__device__ __forceinline__ ull pack2(float x, float y) {
    ull r;
    asm("mov.b64 %0, {%1, %2};" : "=l"(r) : "f"(x), "f"(y));
    return r;
}
__device__ __forceinline__ float2 unpack2(ull v) {
    float2 f;
    asm("mov.b64 {%0, %1}, %2;" : "=f"(f.x), "=f"(f.y) : "l"(v));
    return f;
}

// ---- 1) fused: zero counters || transpose/pack x || bucket scatter --------
// zero blocks are bids 0..24 (scheduled first, wave 1); scatter blocks spin
// on g_done before issuing atomics on g_cnt.
__global__ void __launch_bounds__(512) k_pre(const float* __restrict__ x,
                                             const int2*  __restrict__ idx,
                                             const float* __restrict__ w,
                                             const int*   __restrict__ sids) {
    __shared__ float tile[S][33];
    int tid = threadIdx.x;

    if (blockIdx.x < ZERO_BLKS) {
        // ---- zero g_cnt with int4 stores ----
        int i = blockIdx.x * 512 + tid;              // int4 index
        if (i < (N_POST + 3) / 4)
            ((int4*)g_cnt)[i] = make_int4(0, 0, 0, 0);
        __syncthreads();
        __threadfence();                             // release the zeros
        if (tid == 0) atomicAdd(&g_done, 1);
    } else if (blockIdx.x < ZERO_BLKS + PREP_BLKS) {
        // ---- transpose x[s][c] -> permuted fp16 pack ----
        int tx = tid & 31, ty = tid >> 5;            // (32,16)
        int c0 = (blockIdx.x - ZERO_BLKS) * 32;
        int c = c0 + tx;
        bool cok = (c < N_LGN);
        #pragma unroll
        for (int j = ty; j < S; j += 16)
            tile[j][tx] = cok ? x[j * N_LGN + c] : 0.f;
        __syncthreads();

        uint2* xb = (uint2*)g_xTh;
        #pragma unroll
        for (int cl = ty; cl < 32; cl += 16) {
            int cc = c0 + cl;
            if (cc < N_LGN) {
                __half2 h01 = __floats2half2_rn(tile[tx][cl],      tile[tx + 32][cl]);
                __half2 h23 = __floats2half2_rn(tile[tx + 64][cl], tile[tx + 96][cl]);
                uint2 v;
                v.x = *(unsigned int*)&h01;
                v.y = *(unsigned int*)&h23;
                xb[cc * 32 + tx] = v;
            }
        }
    } else {
        // ---- scatter: wait for zeroing, then 16B meta writes ----
        if (tid == 0) {
            volatile int* vd = &g_done;
            while (*vd < ZERO_BLKS) __nanosleep(64);
        }
        __syncthreads();
        __threadfence();                             // acquire the zeros

        int e = (blockIdx.x - ZERO_BLKS - PREP_BLKS) * 512 + tid;
        if (e < NNZ) {
            int2 rc = idx[e];
            int p = atomicAdd(&g_cnt[rc.x], 1);
            if (p < CAP)
                g_meta[(size_t)rc.x * CAP + p] =
                    make_int4(rc.y * 256, sids[e] * 48, __float_as_int(w[e]), 0);
        }

        // last-finishing scatter block restores handshake state
        __syncthreads();
        __threadfence();
        if (tid == 0) {
            int v = atomicAdd(&g_exit, 1);
            if (v == SCAT_BLKS - 1) { g_done = 0; g_exit = 0; }
        }
    }
}

// ---------------- per-edge math (EXACT R10/R13 source — do not perturb) ----
__device__ __forceinline__ void edge_math(unsigned fa, int w_bits, uint2 xh,
                                          ull acc[NBASIS][2]) {
    float w = __int_as_float(w_bits);
    float2 x01 = __half22float2(*(__half2*)&xh.x);   // s = lane, lane+32
    float2 x23 = __half22float2(*(__half2*)&xh.y);   // s = lane+64, lane+96
    ull ww, xwa, xwc;
    asm("mov.b64 %0, {%1, %1};" : "=l"(ww) : "f"(w));
    ull xa = pack2(x01.x, x01.y);
    ull xc = pack2(x23.x, x23.y);
    asm("mul.rn.f32x2 %0, %1, %2;" : "=l"(xwa) : "l"(xa), "l"(ww));
    asm("mul.rn.f32x2 %0, %1, %2;" : "=l"(xwc) : "l"(xc), "l"(ww));
    ull f0, f1, f2, f3, f4;
    asm("ld.shared.v2.u64 {%0, %1}, [%2];"      : "=l"(f0), "=l"(f1) : "r"(fa));
    asm("ld.shared.v2.u64 {%0, %1}, [%2 + 16];" : "=l"(f2), "=l"(f3) : "r"(fa));
    asm("ld.shared.u64 %0, [%1 + 32];"          : "=l"(f4) : "r"(fa));
    ffma2(acc[0][0], xwa, f0); ffma2(acc[0][1], xwc, f0);
    ffma2(acc[1][0], xwa, f1); ffma2(acc[1][1], xwc, f1);
    ffma2(acc[2][0], xwa, f2); ffma2(acc[2][1], xwc, f2);
    ffma2(acc[3][0], xwa, f3); ffma2(acc[3][1], xwc, f3);
    ffma2(acc[4][0], xwa, f4); ffma2(acc[4][1], xwc, f4);
}

// ---------------- 2) main SpMM (EXACT R13 source — do not perturb) ---------
__global__ void __launch_bounds__(128, 8) k_spmm(float* __restrict__ out,
                                                 const float* __restrict__ synw) {
    __shared__ __align__(16) float  sh[S * 44];          // stride 44: 16B-aligned rows
    __shared__ __align__(16) float2 fsh2[N_RECEPT * 6];  // dup pairs, 48B per sid
    int tid = threadIdx.x;
    if (tid < N_RECEPT * 6) {
        int sid = tid / 6, r = tid - sid * 6;
        float v = (r < NBASIS) ? synw[sid * NBASIS + r] : 0.f;
        fsh2[tid] = make_float2(v, v);
    }
    __syncthreads();
    unsigned fbase = (unsigned)__cvta_generic_to_shared(fsh2);

    int warp = tid >> 5;
    int lane = tid & 31;
    int n0 = blockIdx.x * RPB;
    const char* xlane = (const char*)g_xTh + lane * 8;

    #pragma unroll
    for (int rr = 0; rr < 2; rr++) {
        int n = n0 + warp * 2 + rr;
        int len = g_cnt[n];
        if (len > CAP) len = CAP;
        const int4* pm = g_meta + (size_t)n * CAP;

        ull acc[NBASIS][2];
        #pragma unroll
        for (int r = 0; r < NBASIS; r++) { acc[r][0] = 0ull; acc[r][1] = 0ull; }

        for (int seg = 0; seg * 32 < len; seg++) {
            int4 m = __ldg(pm + seg * 32 + lane);   // 32 edges' meta in warp regs
            int cnt = len - seg * 32;
            if (cnt > 32) cnt = 32;

            int j = 0;
            #pragma unroll 1
            for (; j + 4 <= cnt; j += 4) {
                uint2 xv[4];
                #pragma unroll
                for (int t = 0; t < 4; t++) {
                    int mx = __shfl_sync(0xFFFFFFFFu, m.x, j + t);
                    xv[t] = __ldg((const uint2*)(xlane + mx));   // MLP 4, 2 wf each
                }
                #pragma unroll
                for (int t = 0; t < 4; t++) {
                    int my = __shfl_sync(0xFFFFFFFFu, m.y, j + t);
                    int mw = __shfl_sync(0xFFFFFFFFu, m.z, j + t);
                    edge_math(fbase + (unsigned)my, mw, xv[t], acc);
                }
            }
            for (; j < cnt; j++) {
                int mx = __shfl_sync(0xFFFFFFFFu, m.x, j);
                int my = __shfl_sync(0xFFFFFFFFu, m.y, j);
                int mw = __shfl_sync(0xFFFFFFFFu, m.z, j);
                uint2 xv = __ldg((const uint2*)(xlane + mx));
                edge_math(fbase + (unsigned)my, mw, xv, acc);
            }
        }

        // stage row (warp*2+rr): lane's values are s = {lane, +32, +64, +96}
        int rl = (warp * 2 + rr) * NBASIS;
        #pragma unroll
        for (int r = 0; r < NBASIS; r++) {
            float2 lo = unpack2(acc[r][0]);
            float2 hi = unpack2(acc[r][1]);
            sh[(lane      ) * 44 + rl + r] = lo.x;
            sh[(lane + 32 ) * 44 + rl + r] = lo.y;
            sh[(lane + 64 ) * 44 + rl + r] = hi.x;
            sh[(lane + 96 ) * 44 + rl + r] = hi.y;
        }
    }
    __syncthreads();

    // vectorized write-out: 1280 float4 = 128 s x 10 q; 10 iters per thread
    const float4* sh4 = (const float4*)sh;           // 11 float4 per s-row
    float* op = out + (size_t)n0 * NBASIS;
    #pragma unroll
    for (int it = 0; it < 10; it++) {
        int idx = it * 128 + tid;
        int s = idx / 10;
        int q = idx - s * 10;
        float4 v = sh4[s * 11 + q];
        *(float4*)(op + (size_t)s * OUT_ROW + q * 4) = v;
    }
}

// ---------------- launch ----------------
extern "C" void kernel_launch(void* const* d_in, const int* in_sizes, int n_in,
                              void* d_out, int out_size) {
    const float* inp     = (const float*)d_in[0];
    const int2*  indices = (const int2*)d_in[1];
    const float* weights = (const float*)d_in[2];
    const float* synw    = (const float*)d_in[3];
    const int*   sids    = (const int*)d_in[4];
    float*       out     = (float*)d_out;
    (void)in_sizes; (void)n_in; (void)out_size;

    k_pre<<<ZERO_BLKS + PREP_BLKS + SCAT_BLKS, 512>>>(inp, indices, weights, sids);
    k_spmm<<<N_POST / RPB, 128>>>(out, synw);
}

// round 17
// speedup vs baseline: 1.3607x; 1.0515x over previous
#include <cuda_runtime.h>
#include <cuda_fp16.h>

#define S        128
#define N_LGN    17400
#define N_POST   50000
#define NNZ      800000
#define NBASIS   5
#define N_RECEPT 10
#define OUT_ROW  (N_POST * NBASIS)   // 250000
#define RPB      8                   // rows per block
#define CAP      64                  // bucket capacity (Poisson(16); P(>64) ~ 1e-32)
#define PREP_BLKS 544                // ceil(17400/32)
#define SCAT_BLKS ((NNZ / 2 + 511) / 512)   // 2 edges per thread

// ---------------- device scratch (no allocations allowed) ----------------
// xTh layout: uint2 at [c*32 + lane] = 4 halves x[s = {lane, lane+32, lane+64, lane+96}][c]
__device__ __half g_xTh[N_LGN * S];
__device__ int    g_cnt[N_POST];
__device__ int4   g_meta[(size_t)N_POST * CAP];  // {col*256, sid*48, w_bits, 0}

typedef unsigned long long ull;
__device__ __forceinline__ void ffma2(ull &d, ull a, ull b) {
    asm("fma.rn.f32x2 %0, %1, %2, %0;" : "+l"(d) : "l"(a), "l"(b));
}
__device__ __forceinline__ ull pack2(float x, float y) {
    ull r;
    asm("mov.b64 %0, {%1, %2};" : "=l"(r) : "f"(x), "f"(y));
    return r;
}
__device__ __forceinline__ float2 unpack2(ull v) {
    float2 f;
    asm("mov.b64 {%0, %1}, %2;" : "=f"(f.x), "=f"(f.y) : "l"(v));
    return f;
}

// ------------- 1) fused: transpose/pack x  ||  bucket scatter -------------
__global__ void __launch_bounds__(512) k_pre(const float* __restrict__ x,
                                             const int2*  __restrict__ idx,
                                             const float* __restrict__ w,
                                             const int*   __restrict__ sids) {
    __shared__ float tile[S][33];
    int tid = threadIdx.x;

    if (blockIdx.x < PREP_BLKS) {
        // ---- transpose x[s][c] -> permuted fp16 pack (EXACT R13) ----
        int tx = tid & 31, ty = tid >> 5;    // (32,16)
        int c0 = blockIdx.x * 32;
        int c = c0 + tx;
        bool cok = (c < N_LGN);
        #pragma unroll
        for (int j = ty; j < S; j += 16)
            tile[j][tx] = cok ? x[j * N_LGN + c] : 0.f;
        __syncthreads();

        uint2* xb = (uint2*)g_xTh;
        #pragma unroll
        for (int cl = ty; cl < 32; cl += 16) {
            int cc = c0 + cl;
            if (cc < N_LGN) {
                __half2 h01 = __floats2half2_rn(tile[tx][cl],      tile[tx + 32][cl]);
                __half2 h23 = __floats2half2_rn(tile[tx + 64][cl], tile[tx + 96][cl]);
                uint2 v;
                v.x = *(unsigned int*)&h01;
                v.y = *(unsigned int*)&h23;
                xb[cc * 32 + tx] = v;
            }
        }
    } else {
        // ---- scatter: 2 edges per thread, vectorized loads ----
        int t = (blockIdx.x - PREP_BLKS) * 512 + tid;
        int e0 = t * 2;
        if (e0 >= NNZ) return;
        int4   rc2 = __ldg((const int4*)(idx + e0));     // two int2 pairs
        float2 w2  = __ldg((const float2*)(w + e0));
        int2   s2  = __ldg((const int2*)(sids + e0));

        int p0 = atomicAdd(&g_cnt[rc2.x], 1);
        if (p0 < CAP)
            g_meta[(size_t)rc2.x * CAP + p0] =
                make_int4(rc2.y * 256, s2.x * 48, __float_as_int(w2.x), 0);

        int p1 = atomicAdd(&g_cnt[rc2.z], 1);
        if (p1 < CAP)
            g_meta[(size_t)rc2.z * CAP + p1] =
                make_int4(rc2.w * 256, s2.y * 48, __float_as_int(w2.y), 0);
    }
}

// ---------------- per-edge math (EXACT R10/R13 source — do not perturb) ----
__device__ __forceinline__ void edge_math(unsigned fa, int w_bits, uint2 xh,
                                          ull acc[NBASIS][2]) {
    float w = __int_as_float(w_bits);
    float2 x01 = __half22float2(*(__half2*)&xh.x);   // s = lane, lane+32
    float2 x23 = __half22float2(*(__half2*)&xh.y);   // s = lane+64, lane+96
    ull ww, xwa, xwc;
    asm("mov.b64 %0, {%1, %1};" : "=l"(ww) : "f"(w));
    ull xa = pack2(x01.x, x01.y);
    ull xc = pack2(x23.x, x23.y);
    asm("mul.rn.f32x2 %0, %1, %2;" : "=l"(xwa) : "l"(xa), "l"(ww));
    asm("mul.rn.f32x2 %0, %1, %2;" : "=l"(xwc) : "l"(xc), "l"(ww));
    ull f0, f1, f2, f3, f4;
    asm("ld.shared.v2.u64 {%0, %1}, [%2];"      : "=l"(f0), "=l"(f1) : "r"(fa));
    asm("ld.shared.v2.u64 {%0, %1}, [%2 + 16];" : "=l"(f2), "=l"(f3) : "r"(fa));
    asm("ld.shared.u64 %0, [%1 + 32];"          : "=l"(f4) : "r"(fa));
    ffma2(acc[0][0], xwa, f0); ffma2(acc[0][1], xwc, f0);
    ffma2(acc[1][0], xwa, f1); ffma2(acc[1][1], xwc, f1);
    ffma2(acc[2][0], xwa, f2); ffma2(acc[2][1], xwc, f2);
    ffma2(acc[3][0], xwa, f3); ffma2(acc[3][1], xwc, f3);
    ffma2(acc[4][0], xwa, f4); ffma2(acc[4][1], xwc, f4);
}

// ---------------- 2) main SpMM (EXACT R13 source — do not perturb) ---------
__global__ void __launch_bounds__(128, 8) k_spmm(float* __restrict__ out,
                                                 const float* __restrict__ synw) {
    __shared__ __align__(16) float  sh[S * 44];          // stride 44: 16B-aligned rows
    __shared__ __align__(16) float2 fsh2[N_RECEPT * 6];  // dup pairs, 48B per sid
    int tid = threadIdx.x;
    if (tid < N_RECEPT * 6) {
        int sid = tid / 6, r = tid - sid * 6;
        float v = (r < NBASIS) ? synw[sid * NBASIS + r] : 0.f;
        fsh2[tid] = make_float2(v, v);
    }
    __syncthreads();
    unsigned fbase = (unsigned)__cvta_generic_to_shared(fsh2);

    int warp = tid >> 5;
    int lane = tid & 31;
    int n0 = blockIdx.x * RPB;
    const char* xlane = (const char*)g_xTh + lane * 8;

    #pragma unroll
    for (int rr = 0; rr < 2; rr++) {
        int n = n0 + warp * 2 + rr;
        int len = g_cnt[n];
        if (len > CAP) len = CAP;
        const int4* pm = g_meta + (size_t)n * CAP;

        ull acc[NBASIS][2];
        #pragma unroll
        for (int r = 0; r < NBASIS; r++) { acc[r][0] = 0ull; acc[r][1] = 0ull; }

        for (int seg = 0; seg * 32 < len; seg++) {
            int4 m = __ldg(pm + seg * 32 + lane);   // 32 edges' meta in warp regs
            int cnt = len - seg * 32;
            if (cnt > 32) cnt = 32;

            int j = 0;
            #pragma unroll 1
            for (; j + 4 <= cnt; j += 4) {
                uint2 xv[4];
                #pragma unroll
                for (int t = 0; t < 4; t++) {
                    int mx = __shfl_sync(0xFFFFFFFFu, m.x, j + t);
                    xv[t] = __ldg((const uint2*)(xlane + mx));   // MLP 4, 2 wf each
                }
                #pragma unroll
                for (int t = 0; t < 4; t++) {
                    int my = __shfl_sync(0xFFFFFFFFu, m.y, j + t);
                    int mw = __shfl_sync(0xFFFFFFFFu, m.z, j + t);
                    edge_math(fbase + (unsigned)my, mw, xv[t], acc);
                }
            }
            for (; j < cnt; j++) {
                int mx = __shfl_sync(0xFFFFFFFFu, m.x, j);
                int my = __shfl_sync(0xFFFFFFFFu, m.y, j);
                int mw = __shfl_sync(0xFFFFFFFFu, m.z, j);
                uint2 xv = __ldg((const uint2*)(xlane + mx));
                edge_math(fbase + (unsigned)my, mw, xv, acc);
            }
        }

        // stage row (warp*2+rr): lane's values are s = {lane, +32, +64, +96}
        int rl = (warp * 2 + rr) * NBASIS;
        #pragma unroll
        for (int r = 0; r < NBASIS; r++) {
            float2 lo = unpack2(acc[r][0]);
            float2 hi = unpack2(acc[r][1]);
            sh[(lane      ) * 44 + rl + r] = lo.x;
            sh[(lane + 32 ) * 44 + rl + r] = lo.y;
            sh[(lane + 64 ) * 44 + rl + r] = hi.x;
            sh[(lane + 96 ) * 44 + rl + r] = hi.y;
        }
    }
    __syncthreads();

    // vectorized write-out: 1280 float4 = 128 s x 10 q; 10 iters per thread
    const float4* sh4 = (const float4*)sh;           // 11 float4 per s-row
    float* op = out + (size_t)n0 * NBASIS;
    #pragma unroll
    for (int it = 0; it < 10; it++) {
        int idx = it * 128 + tid;
        int s = idx / 10;
        int q = idx - s * 10;
        float4 v = sh4[s * 11 + q];
        *(float4*)(op + (size_t)s * OUT_ROW + q * 4) = v;
    }
}

// ---------------- launch ----------------
extern "C" void kernel_launch(void* const* d_in, const int* in_sizes, int n_in,
                              void* d_out, int out_size) {
    const float* inp     = (const float*)d_in[0];
    const int2*  indices = (const int2*)d_in[1];
    const float* weights = (const float*)d_in[2];
    const float* synw    = (const float*)d_in[3];
    const int*   sids    = (const int*)d_in[4];
    float*       out     = (float*)d_out;
    (void)in_sizes; (void)n_in; (void)out_size;

    // zero g_cnt via a graph memset node (capture-legal, no allocation)
    void* cnt_ptr = nullptr;
    cudaGetSymbolAddress(&cnt_ptr, g_cnt);
    cudaMemsetAsync(cnt_ptr, 0, N_POST * sizeof(int));

    k_pre<<<PREP_BLKS + SCAT_BLKS, 512>>>(inp, indices, weights, sids);
    k_spmm<<<N_POST / RPB, 128>>>(out, synw);
}